// round 12
// baseline (speedup 1.0000x reference)
#include <cuda_runtime.h>
#include <cuda_fp16.h>
#include <math_constants.h>

#define N_NODES 50000
#define N_EDGES 800000
#define IN_F 128
#define HF    128   // HEADS * OUT_F
#define HEADS 4
#define NEG_SLOPE 0.2f
#define EPSF 1e-8f

#define NBLK 296                      // persistent grid: 2 blocks/SM on 148 SMs
#define GSZ  (NBLK * 256)

// ---------------- scratch (static device globals; no allocations) -------------
__device__ __align__(16) __half g_h[N_NODES * HF];        // 12.8 MB (fp16)
__device__ float  g_Wt[IN_F * HF];                        // W transposed (k-major)
__device__ __align__(16) float g_asrc[N_NODES * HEADS];
__device__ __align__(16) float g_adst[N_NODES * HEADS];
__device__ __align__(8) int2 g_edges[N_EDGES];            // packed (src,dst)
__device__ int  g_cnt[N_NODES];                           // per-dst degree
__device__ int  g_fill[N_NODES];                          // scatter cursors
__device__ int  g_off[N_NODES + 1];                       // CSR offsets
__device__ int  g_bsum[NBLK];                             // per-block scan totals
__device__ int  g_csr_src[N_EDGES];                       // src sorted by dst
__device__ int  g_is64;                                   // dtype flag
__device__ int  g_barrier_cnt;                            // monotonic grid barrier

__device__ __forceinline__ int clampN(int v) {
    v = v < 0 ? 0 : v;
    return v >= N_NODES ? N_NODES - 1 : v;
}

// monotonic ticket grid barrier: safe across graph replays (no reset needed)
__device__ __forceinline__ void grid_sync() {
    __syncthreads();
    if (threadIdx.x == 0) {
        __threadfence();
        int v = atomicAdd(&g_barrier_cnt, 1) + 1;
        int target = ((v + NBLK - 1) / NBLK) * NBLK;
        while (atomicAdd(&g_barrier_cnt, 0) < target) __nanosleep(64);
        __threadfence();
    }
    __syncthreads();
}

// ---------------- fused persistent CSR build ----------------------------------
// P0: zero counters + dtype detect; P1: pack+histogram; P2: scan; P3: scatter
__global__ void __launch_bounds__(256) k_csr_build(const void* __restrict__ ei) {
    const int tid = threadIdx.x;
    const int bid = blockIdx.x;
    const int gt  = bid * 256 + tid;
    const int lane = tid & 31, warp = tid >> 5;

    // ---- P0: zero counters; block 0 warp 0 detects dtype ----
    for (int i = gt; i < N_NODES; i += GSZ) g_cnt[i] = 0;
    if (bid == 0 && tid < 32) {
        const long long* p = (const long long*)ei;
        unsigned hi = 0;
        #pragma unroll
        for (int k = 0; k < 4; ++k)
            hi |= (unsigned)((unsigned long long)p[tid * 4 + k] >> 32);
        unsigned any = __ballot_sync(0xffffffffu, hi != 0);
        if (tid == 0) g_is64 = (any == 0);
    }
    grid_sync();

    // ---- P1: pack edges + histogram dst ----
    const int is64 = *(volatile int*)&g_is64;
    for (int e = gt; e < N_EDGES; e += GSZ) {
        int src, dst;
        if (is64) {
            src = (int)((const long long*)ei)[e];
            dst = (int)((const long long*)ei)[N_EDGES + e];
        } else {
            src = ((const int*)ei)[e];
            dst = ((const int*)ei)[N_EDGES + e];
        }
        src = clampN(src); dst = clampN(dst);
        g_edges[e] = make_int2(src, dst);
        atomicAdd(&g_cnt[dst], 1);
    }
    grid_sync();

    // ---- P2: exclusive scan over g_cnt (block-local + cross-block base) ----
    const int CHN = (N_NODES + NBLK - 1) / NBLK;          // 169 nodes / block
    int nbase = bid * CHN;
    int cntN  = N_NODES - nbase;
    if (cntN < 0) cntN = 0;
    if (cntN > CHN) cntN = CHN;

    int v = (tid < cntN) ? g_cnt[nbase + tid] : 0;

    __shared__ int wsum[8];
    int s = v;
    #pragma unroll
    for (int off = 1; off < 32; off <<= 1) {
        int u = __shfl_up_sync(0xffffffffu, s, off);
        if (lane >= off) s += u;
    }
    if (lane == 31) wsum[warp] = s;
    __syncthreads();
    if (warp == 0) {
        int ws = (lane < 8) ? wsum[lane] : 0;
        #pragma unroll
        for (int off = 1; off < 8; off <<= 1) {
            int u = __shfl_up_sync(0xffffffffu, ws, off);
            if (lane >= off) ws += u;
        }
        if (lane < 8) wsum[lane] = ws;
    }
    __syncthreads();
    int wbase = warp ? wsum[warp - 1] : 0;
    int excl  = wbase + s - v;                             // block-local exclusive
    if (tid == 255) g_bsum[bid] = wbase + s;               // block total
    grid_sync();

    // cross-block base: warp 0 sums g_bsum[0..bid)
    __shared__ int sbase;
    if (tid < 32) {
        int acc = 0;
        for (int i = tid; i < bid; i += 32) acc += g_bsum[i];
        #pragma unroll
        for (int off = 16; off > 0; off >>= 1)
            acc += __shfl_xor_sync(0xffffffffu, acc, off);
        if (tid == 0) sbase = acc;
    }
    __syncthreads();
    if (tid < cntN) {
        int o = excl + sbase;
        g_off[nbase + tid]  = o;
        g_fill[nbase + tid] = o;
    }
    if (bid == NBLK - 1 && tid == 0) g_off[N_NODES] = N_EDGES;
    grid_sync();

    // ---- P3: scatter src into CSR slots ----
    for (int e = gt; e < N_EDGES; e += GSZ) {
        int2 ed = g_edges[e];
        int pos = atomicAdd(&g_fill[ed.y], 1);
        g_csr_src[pos] = ed.x;
    }
}

// ---------------- kernel 1: transpose W ---------------------------------------
__global__ void k_transpose(const float* __restrict__ W) {
    int i = blockIdx.x * 256 + threadIdx.x;
    if (i < HF * IN_F) {
        int j = i / IN_F, k = i % IN_F;
        g_Wt[k * HF + j] = W[i];
    }
}

// ---------------- kernel 2: h = x @ W^T  + alpha epilogue ----------------------
__global__ void __launch_bounds__(256) k_gemm(const float* __restrict__ x,
                                              const float* __restrict__ a_src,
                                              const float* __restrict__ a_dst) {
    __shared__ float xsT[IN_F][65];
    __shared__ float sA[HF], sB[HF];

    int tid = threadIdx.x;
    if (tid < HF) { sA[tid] = a_src[tid]; sB[tid] = a_dst[tid]; }

    int n0 = blockIdx.x * 64;

    #pragma unroll
    for (int it = 0; it < 8; ++it) {
        int flat = tid + it * 256;
        int n  = flat >> 5;
        int kq = flat & 31;
        float4 v = make_float4(0.f, 0.f, 0.f, 0.f);
        int gn = n0 + n;
        if (gn < N_NODES) v = *(const float4*)&x[(size_t)gn * IN_F + kq * 4];
        xsT[kq * 4 + 0][n] = v.x;
        xsT[kq * 4 + 1][n] = v.y;
        xsT[kq * 4 + 2][n] = v.z;
        xsT[kq * 4 + 3][n] = v.w;
    }
    __syncthreads();

    int jq = tid & 31;  int j0 = jq * 4;
    int ng = tid >> 5;  int nb = ng * 8;

    float4 acc[8];
    #pragma unroll
    for (int i = 0; i < 8; ++i) acc[i] = make_float4(0.f, 0.f, 0.f, 0.f);

    #pragma unroll 4
    for (int k = 0; k < IN_F; ++k) {
        float4 wv = *(const float4*)&g_Wt[k * HF + j0];
        #pragma unroll
        for (int i = 0; i < 8; ++i) {
            float xv = xsT[k][nb + i];
            acc[i].x += wv.x * xv;
            acc[i].y += wv.y * xv;
            acc[i].z += wv.z * xv;
            acc[i].w += wv.w * xv;
        }
    }

    int head = jq >> 3;
    #pragma unroll
    for (int i = 0; i < 8; ++i) {
        int gn = n0 + nb + i;
        bool ok = gn < N_NODES;
        if (ok) {
            __half2 h01 = __floats2half2_rn(acc[i].x, acc[i].y);
            __half2 h23 = __floats2half2_rn(acc[i].z, acc[i].w);
            uint2 pk = make_uint2(*(unsigned*)&h01, *(unsigned*)&h23);
            *(uint2*)&g_h[(size_t)gn * HF + j0] = pk;
        }
        float s1 = acc[i].x * sA[j0] + acc[i].y * sA[j0 + 1] +
                   acc[i].z * sA[j0 + 2] + acc[i].w * sA[j0 + 3];
        float s2 = acc[i].x * sB[j0] + acc[i].y * sB[j0 + 1] +
                   acc[i].z * sB[j0 + 2] + acc[i].w * sB[j0 + 3];
        #pragma unroll
        for (int off = 1; off < 8; off <<= 1) {
            s1 += __shfl_xor_sync(0xffffffffu, s1, off);
            s2 += __shfl_xor_sync(0xffffffffu, s2, off);
        }
        if (ok && (jq & 7) == 0) {
            g_asrc[gn * HEADS + head] = s1;
            g_adst[gn * HEADS + head] = s2;
        }
    }
}

// ---------------- kernel 3: CSR aggregation (warp per dst node) ----------------
// phase B processes 2 edges/iteration; each lane loads 16B (8 halves).
#define CHUNK 64
__global__ void __launch_bounds__(256) k_agg(float* __restrict__ out) {
    __shared__ float4 sh_exp[8][CHUNK];
    __shared__ int    sh_src[8][CHUNK];

    int w    = threadIdx.x >> 5;
    int lane = threadIdx.x & 31;
    int n    = blockIdx.x * 8 + w;
    if (n >= N_NODES) return;

    int start = g_off[n];
    int end   = g_off[n + 1];

    int e2 = lane >> 4;          // edge slot within pair (0/1)
    int q  = lane & 15;          // feature octet: features q*8 .. q*8+7
    int headq = q >> 2;          // head of this octet

    float acc[8] = {0.f, 0.f, 0.f, 0.f, 0.f, 0.f, 0.f, 0.f};
    float4 sum = make_float4(0.f, 0.f, 0.f, 0.f);

    if (start < end) {
        float4 b4 = *(const float4*)&g_adst[n * HEADS];

        for (int cs = start; cs < end; cs += CHUNK) {
            int cnt = min(end - cs, CHUNK);
            // phase A: lane-parallel logits -> exp
            for (int k = lane; k < cnt; k += 32) {
                int src = g_csr_src[cs + k];
                float4 a = *(const float4*)&g_asrc[src * HEADS];
                float v0 = a.x + b4.x, v1 = a.y + b4.y;
                float v2 = a.z + b4.z, v3 = a.w + b4.w;
                v0 = v0 > 0.f ? v0 : NEG_SLOPE * v0;
                v1 = v1 > 0.f ? v1 : NEG_SLOPE * v1;
                v2 = v2 > 0.f ? v2 : NEG_SLOPE * v2;
                v3 = v3 > 0.f ? v3 : NEG_SLOPE * v3;
                float4 ex = make_float4(__expf(v0), __expf(v1), __expf(v2), __expf(v3));
                sh_exp[w][k] = ex;
                sh_src[w][k] = src;
                sum.x += ex.x; sum.y += ex.y; sum.z += ex.z; sum.w += ex.w;
            }
            __syncwarp();
            // phase B: 2 edges per iteration, 16B gather per lane
            #pragma unroll 4
            for (int k = 0; k < cnt; k += 2) {
                int kk = k + e2;
                float att = 0.f;
                int src = sh_src[w][k];
                if (kk < cnt) {
                    att = ((const float*)&sh_exp[w][kk])[headq];
                    src = sh_src[w][kk];
                }
                uint4 pk = *(const uint4*)&g_h[(size_t)src * HF + q * 8];
                float2 f0 = __half22float2(*(const __half2*)&pk.x);
                float2 f1 = __half22float2(*(const __half2*)&pk.y);
                float2 f2 = __half22float2(*(const __half2*)&pk.z);
                float2 f3 = __half22float2(*(const __half2*)&pk.w);
                acc[0] += att * f0.x; acc[1] += att * f0.y;
                acc[2] += att * f1.x; acc[3] += att * f1.y;
                acc[4] += att * f2.x; acc[5] += att * f2.y;
                acc[6] += att * f3.x; acc[7] += att * f3.y;
            }
            __syncwarp();
        }

        // combine edge-pair partials
        #pragma unroll
        for (int j = 0; j < 8; ++j)
            acc[j] += __shfl_xor_sync(0xffffffffu, acc[j], 16);

        // warp-reduce exp sums (all heads)
        #pragma unroll
        for (int off = 1; off < 32; off <<= 1) {
            sum.x += __shfl_xor_sync(0xffffffffu, sum.x, off);
            sum.y += __shfl_xor_sync(0xffffffffu, sum.y, off);
            sum.z += __shfl_xor_sync(0xffffffffu, sum.z, off);
            sum.w += __shfl_xor_sync(0xffffffffu, sum.w, off);
        }
        float sh = ((const float*)&sum)[headq];
        float inv = 1.f / (sh + EPSF);
        #pragma unroll
        for (int j = 0; j < 8; ++j) acc[j] *= inv;
    }

    if (e2 == 0) {
        float4 o0 = make_float4(acc[0], acc[1], acc[2], acc[3]);
        float4 o1 = make_float4(acc[4], acc[5], acc[6], acc[7]);
        *(float4*)&out[(size_t)n * HF + q * 8]     = o0;
        *(float4*)&out[(size_t)n * HF + q * 8 + 4] = o1;
    }
}

// ---------------- launch (fork/join two independent chains) --------------------
extern "C" void kernel_launch(void* const* d_in, const int* in_sizes, int n_in,
                              void* d_out, int out_size) {
    const float* x     = (const float*)d_in[0];
    const void*  ei    = d_in[1];
    const float* W     = (const float*)d_in[2];
    const float* a_src = (const float*)d_in[3];
    const float* a_dst = (const float*)d_in[4];
    float*       out   = (float*)d_out;

    static cudaStream_t sA = nullptr;
    static cudaEvent_t  evFork = nullptr, evJoin = nullptr;
    if (!sA) {
        cudaStreamCreateWithFlags(&sA, cudaStreamNonBlocking);
        cudaEventCreateWithFlags(&evFork, cudaEventDisableTiming);
        cudaEventCreateWithFlags(&evJoin, cudaEventDisableTiming);
    }

    // fork: branch A (fused CSR build) on sA, branch B (transpose+gemm) on 0
    cudaEventRecord(evFork, 0);
    cudaStreamWaitEvent(sA, evFork, 0);

    k_csr_build<<<NBLK, 256, 0, sA>>>(ei);
    cudaEventRecord(evJoin, sA);

    k_transpose<<<(HF * IN_F + 255) / 256, 256>>>(W);
    k_gemm<<<(N_NODES + 63) / 64, 256>>>(x, a_src, a_dst);

    cudaStreamWaitEvent(0, evJoin, 0);
    k_agg<<<(N_NODES + 7) / 8, 256>>>(out);
}

// round 13
// speedup vs baseline: 1.1336x; 1.1336x over previous
#include <cuda_runtime.h>
#include <cuda_fp16.h>
#include <math_constants.h>

#define N_NODES 50000
#define N_EDGES 800000
#define IN_F 128
#define HF    128   // HEADS * OUT_F
#define HEADS 4
#define NEG_SLOPE 0.2f
#define EPSF 1e-8f

#define SCAN_B 1024
#define N_SCAN_BLOCKS ((N_NODES + SCAN_B - 1) / SCAN_B)   // 49

// ---------------- scratch (static device globals; no allocations) -------------
__device__ __align__(16) __half g_h[N_NODES * HF];        // 12.8 MB (fp16)
__device__ float  g_Wt[IN_F * HF];                        // W transposed (k-major)
__device__ __align__(16) float g_asrc[N_NODES * HEADS];
__device__ __align__(16) float g_adst[N_NODES * HEADS];
__device__ __align__(8) int2 g_edges[N_EDGES];            // packed (src,dst)
__device__ int  g_cnt[N_NODES];                           // per-dst degree
__device__ int  g_fill[N_NODES];                          // scatter cursors
__device__ int  g_off[N_NODES + 1];                       // CSR offsets
__device__ int  g_bsum[N_SCAN_BLOCKS];                    // per-block totals
__device__ int  g_csr_src[N_EDGES];                       // src sorted by dst
__device__ int  g_is64;                                   // dtype flag

__device__ __forceinline__ int clampN(int v) {
    v = v < 0 ? 0 : v;
    return v >= N_NODES ? N_NODES - 1 : v;
}

// ---------------- kernel 0: zero counters + dtype detect (block 0) -------------
__global__ void k_zero_detect(const void* __restrict__ ei) {
    int i = blockIdx.x * 256 + threadIdx.x;
    if (i < N_NODES) g_cnt[i] = 0;
    if (blockIdx.x == 0 && threadIdx.x < 32) {
        const long long* p = (const long long*)ei;
        int lane = threadIdx.x;
        unsigned hi = 0;
        #pragma unroll
        for (int k = 0; k < 4; ++k)
            hi |= (unsigned)((unsigned long long)p[lane * 4 + k] >> 32);
        unsigned any = __ballot_sync(0xffffffffu, hi != 0);
        if (lane == 0) g_is64 = (any == 0);
    }
}

// ---------------- kernel 0b: pack edges + histogram dst -----------------------
__global__ void k_pack(const void* __restrict__ ei) {
    int e = blockIdx.x * 256 + threadIdx.x;
    if (e >= N_EDGES) return;
    int src, dst;
    if (g_is64) {
        src = (int)((const long long*)ei)[e];
        dst = (int)((const long long*)ei)[N_EDGES + e];
    } else {
        src = ((const int*)ei)[e];
        dst = ((const int*)ei)[N_EDGES + e];
    }
    src = clampN(src); dst = clampN(dst);
    g_edges[e] = make_int2(src, dst);
    atomicAdd(&g_cnt[dst], 1);
}

// ---------------- scan stage 1: per-block exclusive scan -----------------------
__global__ void __launch_bounds__(SCAN_B) k_scan1() {
    __shared__ int wsum[32];
    int t = threadIdx.x;
    int i = blockIdx.x * SCAN_B + t;
    int v = (i < N_NODES) ? g_cnt[i] : 0;

    int lane = t & 31, warp = t >> 5;
    int s = v;
    #pragma unroll
    for (int off = 1; off < 32; off <<= 1) {
        int u = __shfl_up_sync(0xffffffffu, s, off);
        if (lane >= off) s += u;
    }
    if (lane == 31) wsum[warp] = s;
    __syncthreads();
    if (warp == 0) {
        int ws = wsum[lane];
        #pragma unroll
        for (int off = 1; off < 32; off <<= 1) {
            int u = __shfl_up_sync(0xffffffffu, ws, off);
            if (lane >= off) ws += u;
        }
        wsum[lane] = ws;
    }
    __syncthreads();
    int base = warp ? wsum[warp - 1] : 0;
    int excl = base + s - v;
    if (i < N_NODES) g_off[i] = excl;
    if (t == SCAN_B - 1) g_bsum[blockIdx.x] = base + s;
}

// ---------------- scan stage 2: scan the 49 block totals -----------------------
__global__ void k_scan2() {
    __shared__ int sm[N_SCAN_BLOCKS];
    int t = threadIdx.x;
    if (t < N_SCAN_BLOCKS) sm[t] = g_bsum[t];
    __syncthreads();
    if (t == 0) {
        int run = 0;
        for (int i = 0; i < N_SCAN_BLOCKS; ++i) {
            int c = sm[i]; sm[i] = run; run += c;
        }
        g_off[N_NODES] = N_EDGES;
    }
    __syncthreads();
    if (t < N_SCAN_BLOCKS) g_bsum[t] = sm[t];
}

// ---------------- scan stage 3: add block bases + seed cursors ------------------
__global__ void __launch_bounds__(SCAN_B) k_scan3() {
    int i = blockIdx.x * SCAN_B + threadIdx.x;
    if (i < N_NODES) {
        int o = g_off[i] + g_bsum[blockIdx.x];
        g_off[i] = o;
        g_fill[i] = o;
    }
}

// ---------------- kernel 0d: scatter src into CSR slots ------------------------
__global__ void k_scatter() {
    int e = blockIdx.x * 256 + threadIdx.x;
    if (e >= N_EDGES) return;
    int2 ed = g_edges[e];
    int pos = atomicAdd(&g_fill[ed.y], 1);
    g_csr_src[pos] = ed.x;
}

// ---------------- kernel 1: transpose W ---------------------------------------
__global__ void k_transpose(const float* __restrict__ W) {
    int i = blockIdx.x * 256 + threadIdx.x;
    if (i < HF * IN_F) {
        int j = i / IN_F, k = i % IN_F;
        g_Wt[k * HF + j] = W[i];
    }
}

// ---------------- kernel 2: h = x @ W^T  + alpha epilogue ----------------------
__global__ void __launch_bounds__(256) k_gemm(const float* __restrict__ x,
                                              const float* __restrict__ a_src,
                                              const float* __restrict__ a_dst) {
    __shared__ float xsT[IN_F][65];
    __shared__ float sA[HF], sB[HF];

    int tid = threadIdx.x;
    if (tid < HF) { sA[tid] = a_src[tid]; sB[tid] = a_dst[tid]; }

    int n0 = blockIdx.x * 64;

    #pragma unroll
    for (int it = 0; it < 8; ++it) {
        int flat = tid + it * 256;
        int n  = flat >> 5;
        int kq = flat & 31;
        float4 v = make_float4(0.f, 0.f, 0.f, 0.f);
        int gn = n0 + n;
        if (gn < N_NODES) v = *(const float4*)&x[(size_t)gn * IN_F + kq * 4];
        xsT[kq * 4 + 0][n] = v.x;
        xsT[kq * 4 + 1][n] = v.y;
        xsT[kq * 4 + 2][n] = v.z;
        xsT[kq * 4 + 3][n] = v.w;
    }
    __syncthreads();

    int jq = tid & 31;  int j0 = jq * 4;
    int ng = tid >> 5;  int nb = ng * 8;

    float4 acc[8];
    #pragma unroll
    for (int i = 0; i < 8; ++i) acc[i] = make_float4(0.f, 0.f, 0.f, 0.f);

    #pragma unroll 4
    for (int k = 0; k < IN_F; ++k) {
        float4 wv = *(const float4*)&g_Wt[k * HF + j0];
        #pragma unroll
        for (int i = 0; i < 8; ++i) {
            float xv = xsT[k][nb + i];
            acc[i].x += wv.x * xv;
            acc[i].y += wv.y * xv;
            acc[i].z += wv.z * xv;
            acc[i].w += wv.w * xv;
        }
    }

    int head = jq >> 3;
    #pragma unroll
    for (int i = 0; i < 8; ++i) {
        int gn = n0 + nb + i;
        bool ok = gn < N_NODES;
        if (ok) {
            __half2 h01 = __floats2half2_rn(acc[i].x, acc[i].y);
            __half2 h23 = __floats2half2_rn(acc[i].z, acc[i].w);
            uint2 pk = make_uint2(*(unsigned*)&h01, *(unsigned*)&h23);
            *(uint2*)&g_h[(size_t)gn * HF + j0] = pk;
        }
        float s1 = acc[i].x * sA[j0] + acc[i].y * sA[j0 + 1] +
                   acc[i].z * sA[j0 + 2] + acc[i].w * sA[j0 + 3];
        float s2 = acc[i].x * sB[j0] + acc[i].y * sB[j0 + 1] +
                   acc[i].z * sB[j0 + 2] + acc[i].w * sB[j0 + 3];
        #pragma unroll
        for (int off = 1; off < 8; off <<= 1) {
            s1 += __shfl_xor_sync(0xffffffffu, s1, off);
            s2 += __shfl_xor_sync(0xffffffffu, s2, off);
        }
        if (ok && (jq & 7) == 0) {
            g_asrc[gn * HEADS + head] = s1;
            g_adst[gn * HEADS + head] = s2;
        }
    }
}

// ---------------- kernel 3: CSR aggregation (warp per dst node) ----------------
// phase B: 2 edges/iteration; each lane loads 16B (8 halves). Padded to even cnt.
#define CHUNK 64
__global__ void __launch_bounds__(256) k_agg(float* __restrict__ out) {
    __shared__ float4 sh_exp[8][CHUNK];
    __shared__ int    sh_src[8][CHUNK];

    int w    = threadIdx.x >> 5;
    int lane = threadIdx.x & 31;
    int n    = blockIdx.x * 8 + w;
    if (n >= N_NODES) return;

    int start = g_off[n];
    int end   = g_off[n + 1];

    int e2 = lane >> 4;          // edge slot within pair (0/1)
    int q  = lane & 15;          // feature octet: features q*8 .. q*8+7
    int headq = q >> 2;          // head of this octet

    float acc[8] = {0.f, 0.f, 0.f, 0.f, 0.f, 0.f, 0.f, 0.f};
    float4 sum = make_float4(0.f, 0.f, 0.f, 0.f);

    if (start < end) {
        float4 b4 = *(const float4*)&g_adst[n * HEADS];

        for (int cs = start; cs < end; cs += CHUNK) {
            int cnt = min(end - cs, CHUNK);
            // phase A: lane-parallel logits -> exp
            for (int k = lane; k < cnt; k += 32) {
                int src = g_csr_src[cs + k];
                float4 a = *(const float4*)&g_asrc[src * HEADS];
                float v0 = a.x + b4.x, v1 = a.y + b4.y;
                float v2 = a.z + b4.z, v3 = a.w + b4.w;
                v0 = v0 > 0.f ? v0 : NEG_SLOPE * v0;
                v1 = v1 > 0.f ? v1 : NEG_SLOPE * v1;
                v2 = v2 > 0.f ? v2 : NEG_SLOPE * v2;
                v3 = v3 > 0.f ? v3 : NEG_SLOPE * v3;
                float4 ex = make_float4(__expf(v0), __expf(v1), __expf(v2), __expf(v3));
                sh_exp[w][k] = ex;
                sh_src[w][k] = src;
                sum.x += ex.x; sum.y += ex.y; sum.z += ex.z; sum.w += ex.w;
            }
            // pad to even: zero-exp sentinel (contributes nothing)
            if (lane == 0 && (cnt & 1)) {
                sh_exp[w][cnt] = make_float4(0.f, 0.f, 0.f, 0.f);
                sh_src[w][cnt] = sh_src[w][0];
            }
            __syncwarp();
            int cnt2 = (cnt + 1) & ~1;
            // phase B: 2 edges per iteration, 16B gather per lane, branch-free
            #pragma unroll 4
            for (int k = 0; k < cnt2; k += 2) {
                int kk = k + e2;
                float att = ((const float*)&sh_exp[w][kk])[headq];
                int src = sh_src[w][kk];
                uint4 pk = *(const uint4*)&g_h[(size_t)src * HF + q * 8];
                float2 f0 = __half22float2(*(const __half2*)&pk.x);
                float2 f1 = __half22float2(*(const __half2*)&pk.y);
                float2 f2 = __half22float2(*(const __half2*)&pk.z);
                float2 f3 = __half22float2(*(const __half2*)&pk.w);
                acc[0] += att * f0.x; acc[1] += att * f0.y;
                acc[2] += att * f1.x; acc[3] += att * f1.y;
                acc[4] += att * f2.x; acc[5] += att * f2.y;
                acc[6] += att * f3.x; acc[7] += att * f3.y;
            }
            __syncwarp();
        }

        // combine edge-pair partials
        #pragma unroll
        for (int j = 0; j < 8; ++j)
            acc[j] += __shfl_xor_sync(0xffffffffu, acc[j], 16);

        // warp-reduce exp sums (all heads)
        #pragma unroll
        for (int off = 1; off < 32; off <<= 1) {
            sum.x += __shfl_xor_sync(0xffffffffu, sum.x, off);
            sum.y += __shfl_xor_sync(0xffffffffu, sum.y, off);
            sum.z += __shfl_xor_sync(0xffffffffu, sum.z, off);
            sum.w += __shfl_xor_sync(0xffffffffu, sum.w, off);
        }
        float sh = ((const float*)&sum)[headq];
        float inv = 1.f / (sh + EPSF);
        #pragma unroll
        for (int j = 0; j < 8; ++j) acc[j] *= inv;
    }

    if (e2 == 0) {
        float4 o0 = make_float4(acc[0], acc[1], acc[2], acc[3]);
        float4 o1 = make_float4(acc[4], acc[5], acc[6], acc[7]);
        *(float4*)&out[(size_t)n * HF + q * 8]     = o0;
        *(float4*)&out[(size_t)n * HF + q * 8 + 4] = o1;
    }
}

// ---------------- launch (fork/join two independent chains) --------------------
extern "C" void kernel_launch(void* const* d_in, const int* in_sizes, int n_in,
                              void* d_out, int out_size) {
    const float* x     = (const float*)d_in[0];
    const void*  ei    = d_in[1];
    const float* W     = (const float*)d_in[2];
    const float* a_src = (const float*)d_in[3];
    const float* a_dst = (const float*)d_in[4];
    float*       out   = (float*)d_out;

    static cudaStream_t sA = nullptr;
    static cudaEvent_t  evFork = nullptr, evJoin = nullptr;
    if (!sA) {
        cudaStreamCreateWithFlags(&sA, cudaStreamNonBlocking);
        cudaEventCreateWithFlags(&evFork, cudaEventDisableTiming);
        cudaEventCreateWithFlags(&evJoin, cudaEventDisableTiming);
    }

    // fork: branch A (CSR build) on sA, branch B (transpose+gemm) on stream 0
    cudaEventRecord(evFork, 0);
    cudaStreamWaitEvent(sA, evFork, 0);

    // branch A: CSR build
    k_zero_detect<<<(N_NODES + 255) / 256, 256, 0, sA>>>(ei);
    k_pack<<<(N_EDGES + 255) / 256, 256, 0, sA>>>(ei);
    k_scan1<<<N_SCAN_BLOCKS, SCAN_B, 0, sA>>>();
    k_scan2<<<1, 64, 0, sA>>>();
    k_scan3<<<N_SCAN_BLOCKS, SCAN_B, 0, sA>>>();
    k_scatter<<<(N_EDGES + 255) / 256, 256, 0, sA>>>();
    cudaEventRecord(evJoin, sA);

    // branch B: feature transform
    k_transpose<<<(HF * IN_F + 255) / 256, 256>>>(W);
    k_gemm<<<(N_NODES + 63) / 64, 256>>>(x, a_src, a_dst);

    // join, then aggregate
    cudaStreamWaitEvent(0, evJoin, 0);
    k_agg<<<(N_NODES + 7) / 8, 256>>>(out);
}

// round 15
// speedup vs baseline: 1.1858x; 1.0461x over previous
#include <cuda_runtime.h>
#include <cuda_fp16.h>
#include <math_constants.h>

#define N_NODES 50000
#define N_EDGES 800000
#define IN_F 128
#define HF    128   // HEADS * OUT_F
#define HEADS 4
#define NEG_SLOPE 0.2f
#define EPSF 1e-8f

#define SCAN_B 1024
#define N_SCAN_BLOCKS ((N_NODES + SCAN_B - 1) / SCAN_B)   // 49

// packed fp32x2 ops (sm_103a FFMA2 — only reachable via PTX)
#define FMA_F32X2(d, a, b, c) \
    asm("fma.rn.f32x2 %0, %1, %2, %3;" : "=l"(d) : "l"(a), "l"(b), "l"(c))
#define PACKF2(out, lo, hi) \
    asm("mov.b64 %0, {%1, %2};" : "=l"(out) : "f"(lo), "f"(hi))
#define UNPACKF2(lo, hi, in) \
    asm("mov.b64 {%0, %1}, %2;" : "=f"(lo), "=f"(hi) : "l"(in))

// ---------------- scratch (static device globals; no allocations) -------------
__device__ __align__(16) __half g_h[N_NODES * HF];        // 12.8 MB (fp16)
__device__ float  g_Wt[IN_F * HF];                        // W transposed (k-major)
__device__ __align__(16) float g_asrc[N_NODES * HEADS];
__device__ __align__(16) float g_adst[N_NODES * HEADS];
__device__ __align__(8) int2 g_edges[N_EDGES];            // packed (src,dst)
__device__ int  g_cnt[N_NODES];                           // per-dst degree
__device__ int  g_fill[N_NODES];                          // scatter cursors
__device__ int  g_off[N_NODES + 1];                       // CSR offsets
__device__ int  g_bsum[N_SCAN_BLOCKS];                    // per-block totals
__device__ int  g_csr_src[N_EDGES];                       // src sorted by dst
__device__ int  g_is64;                                   // dtype flag

__device__ __forceinline__ int clampN(int v) {
    v = v < 0 ? 0 : v;
    return v >= N_NODES ? N_NODES - 1 : v;
}

// ---------------- kernel 0: zero counters + dtype detect (block 0) -------------
__global__ void k_zero_detect(const void* __restrict__ ei) {
    int i = blockIdx.x * 256 + threadIdx.x;
    if (i < N_NODES) g_cnt[i] = 0;
    if (blockIdx.x == 0 && threadIdx.x < 32) {
        const long long* p = (const long long*)ei;
        int lane = threadIdx.x;
        unsigned hi = 0;
        #pragma unroll
        for (int k = 0; k < 4; ++k)
            hi |= (unsigned)((unsigned long long)p[lane * 4 + k] >> 32);
        unsigned any = __ballot_sync(0xffffffffu, hi != 0);
        if (lane == 0) g_is64 = (any == 0);
    }
}

// ---------------- kernel 0b: pack edges + histogram dst -----------------------
__global__ void k_pack(const void* __restrict__ ei) {
    int e = blockIdx.x * 256 + threadIdx.x;
    if (e >= N_EDGES) return;
    int src, dst;
    if (g_is64) {
        src = (int)((const long long*)ei)[e];
        dst = (int)((const long long*)ei)[N_EDGES + e];
    } else {
        src = ((const int*)ei)[e];
        dst = ((const int*)ei)[N_EDGES + e];
    }
    src = clampN(src); dst = clampN(dst);
    g_edges[e] = make_int2(src, dst);
    atomicAdd(&g_cnt[dst], 1);
}

// ---------------- scan stage 1: per-block exclusive scan -----------------------
__global__ void __launch_bounds__(SCAN_B) k_scan1() {
    __shared__ int wsum[32];
    int t = threadIdx.x;
    int i = blockIdx.x * SCAN_B + t;
    int v = (i < N_NODES) ? g_cnt[i] : 0;

    int lane = t & 31, warp = t >> 5;
    int s = v;
    #pragma unroll
    for (int off = 1; off < 32; off <<= 1) {
        int u = __shfl_up_sync(0xffffffffu, s, off);
        if (lane >= off) s += u;
    }
    if (lane == 31) wsum[warp] = s;
    __syncthreads();
    if (warp == 0) {
        int ws = wsum[lane];
        #pragma unroll
        for (int off = 1; off < 32; off <<= 1) {
            int u = __shfl_up_sync(0xffffffffu, ws, off);
            if (lane >= off) ws += u;
        }
        wsum[lane] = ws;
    }
    __syncthreads();
    int base = warp ? wsum[warp - 1] : 0;
    int excl = base + s - v;
    if (i < N_NODES) g_off[i] = excl;
    if (t == SCAN_B - 1) g_bsum[blockIdx.x] = base + s;
}

// ---------------- scan stage 2: scan the 49 block totals -----------------------
__global__ void k_scan2() {
    __shared__ int sm[N_SCAN_BLOCKS];
    int t = threadIdx.x;
    if (t < N_SCAN_BLOCKS) sm[t] = g_bsum[t];
    __syncthreads();
    if (t == 0) {
        int run = 0;
        for (int i = 0; i < N_SCAN_BLOCKS; ++i) {
            int c = sm[i]; sm[i] = run; run += c;
        }
        g_off[N_NODES] = N_EDGES;
    }
    __syncthreads();
    if (t < N_SCAN_BLOCKS) g_bsum[t] = sm[t];
}

// ---------------- scan stage 3: add block bases + seed cursors ------------------
__global__ void __launch_bounds__(SCAN_B) k_scan3() {
    int i = blockIdx.x * SCAN_B + threadIdx.x;
    if (i < N_NODES) {
        int o = g_off[i] + g_bsum[blockIdx.x];
        g_off[i] = o;
        g_fill[i] = o;
    }
}

// ---------------- kernel 0d: scatter src into CSR slots ------------------------
__global__ void k_scatter() {
    int e = blockIdx.x * 256 + threadIdx.x;
    if (e >= N_EDGES) return;
    int2 ed = g_edges[e];
    int pos = atomicAdd(&g_fill[ed.y], 1);
    g_csr_src[pos] = ed.x;
}

// ---------------- kernel 1: transpose W ---------------------------------------
__global__ void k_transpose(const float* __restrict__ W) {
    int i = blockIdx.x * 256 + threadIdx.x;
    if (i < HF * IN_F) {
        int j = i / IN_F, k = i % IN_F;
        g_Wt[k * HF + j] = W[i];
    }
}

// ---------------- kernel 2: h = x @ W^T via FFMA2 + alpha epilogue -------------
// accumulators pair adjacent nodes in fp32x2 lanes (2x FMA throughput)
__global__ void __launch_bounds__(256) k_gemm(const float* __restrict__ x,
                                              const float* __restrict__ a_src,
                                              const float* __restrict__ a_dst) {
    __shared__ float xsT[IN_F][65];
    __shared__ float sA[HF], sB[HF];

    int tid = threadIdx.x;
    if (tid < HF) { sA[tid] = a_src[tid]; sB[tid] = a_dst[tid]; }

    int n0 = blockIdx.x * 64;

    #pragma unroll
    for (int it = 0; it < 8; ++it) {
        int flat = tid + it * 256;
        int n  = flat >> 5;
        int kq = flat & 31;
        float4 v = make_float4(0.f, 0.f, 0.f, 0.f);
        int gn = n0 + n;
        if (gn < N_NODES) v = *(const float4*)&x[(size_t)gn * IN_F + kq * 4];
        xsT[kq * 4 + 0][n] = v.x;
        xsT[kq * 4 + 1][n] = v.y;
        xsT[kq * 4 + 2][n] = v.z;
        xsT[kq * 4 + 3][n] = v.w;
    }
    __syncthreads();

    int jq = tid & 31;  int j0 = jq * 4;
    int ng = tid >> 5;  int nb = ng * 8;

    // accp[p][c]: fp32x2 accumulator for nodes (nb+2p, nb+2p+1), j-component c
    unsigned long long accp[4][4];
    #pragma unroll
    for (int p = 0; p < 4; ++p)
        #pragma unroll
        for (int c = 0; c < 4; ++c) accp[p][c] = 0ULL;

    #pragma unroll 4
    for (int k = 0; k < IN_F; ++k) {
        float4 wv = *(const float4*)&g_Wt[k * HF + j0];   // coalesced, L1-hit
        unsigned long long wx, wy, wz, ww;
        PACKF2(wx, wv.x, wv.x);
        PACKF2(wy, wv.y, wv.y);
        PACKF2(wz, wv.z, wv.z);
        PACKF2(ww, wv.w, wv.w);
        #pragma unroll
        for (int p = 0; p < 4; ++p) {
            float x0 = xsT[k][nb + 2 * p];                // broadcast LDS
            float x1 = xsT[k][nb + 2 * p + 1];
            unsigned long long xp;
            PACKF2(xp, x0, x1);
            FMA_F32X2(accp[p][0], xp, wx, accp[p][0]);
            FMA_F32X2(accp[p][1], xp, wy, accp[p][1]);
            FMA_F32X2(accp[p][2], xp, wz, accp[p][2]);
            FMA_F32X2(accp[p][3], xp, ww, accp[p][3]);
        }
    }

    // unpack into per-node accumulators
    float4 acc[8];
    #pragma unroll
    for (int p = 0; p < 4; ++p) {
        float lx, hx, ly, hy, lz, hz, lw, hw;
        UNPACKF2(lx, hx, accp[p][0]);
        UNPACKF2(ly, hy, accp[p][1]);
        UNPACKF2(lz, hz, accp[p][2]);
        UNPACKF2(lw, hw, accp[p][3]);
        acc[2 * p]     = make_float4(lx, ly, lz, lw);
        acc[2 * p + 1] = make_float4(hx, hy, hz, hw);
    }

    int head = jq >> 3;
    #pragma unroll
    for (int i = 0; i < 8; ++i) {
        int gn = n0 + nb + i;
        bool ok = gn < N_NODES;
        if (ok) {
            __half2 h01 = __floats2half2_rn(acc[i].x, acc[i].y);
            __half2 h23 = __floats2half2_rn(acc[i].z, acc[i].w);
            uint2 pk = make_uint2(*(unsigned*)&h01, *(unsigned*)&h23);
            *(uint2*)&g_h[(size_t)gn * HF + j0] = pk;
        }
        float s1 = acc[i].x * sA[j0] + acc[i].y * sA[j0 + 1] +
                   acc[i].z * sA[j0 + 2] + acc[i].w * sA[j0 + 3];
        float s2 = acc[i].x * sB[j0] + acc[i].y * sB[j0 + 1] +
                   acc[i].z * sB[j0 + 2] + acc[i].w * sB[j0 + 3];
        #pragma unroll
        for (int off = 1; off < 8; off <<= 1) {
            s1 += __shfl_xor_sync(0xffffffffu, s1, off);
            s2 += __shfl_xor_sync(0xffffffffu, s2, off);
        }
        if (ok && (jq & 7) == 0) {
            g_asrc[gn * HEADS + head] = s1;
            g_adst[gn * HEADS + head] = s2;
        }
    }
}

// ---------------- kernel 3: CSR aggregation (warp per dst node) ----------------
// phase B: 2 edges/iteration; each lane loads 16B (8 halves). Padded to even cnt.
#define CHUNK 64
__global__ void __launch_bounds__(256) k_agg(float* __restrict__ out) {
    __shared__ float4 sh_exp[8][CHUNK];
    __shared__ int    sh_src[8][CHUNK];

    int w    = threadIdx.x >> 5;
    int lane = threadIdx.x & 31;
    int n    = blockIdx.x * 8 + w;
    if (n >= N_NODES) return;

    int start = g_off[n];
    int end   = g_off[n + 1];

    int e2 = lane >> 4;          // edge slot within pair (0/1)
    int q  = lane & 15;          // feature octet: features q*8 .. q*8+7
    int headq = q >> 2;          // head of this octet

    float acc[8] = {0.f, 0.f, 0.f, 0.f, 0.f, 0.f, 0.f, 0.f};
    float4 sum = make_float4(0.f, 0.f, 0.f, 0.f);

    if (start < end) {
        float4 b4 = *(const float4*)&g_adst[n * HEADS];

        for (int cs = start; cs < end; cs += CHUNK) {
            int cnt = min(end - cs, CHUNK);
            // phase A: lane-parallel logits -> exp
            for (int k = lane; k < cnt; k += 32) {
                int src = g_csr_src[cs + k];
                float4 a = *(const float4*)&g_asrc[src * HEADS];
                float v0 = a.x + b4.x, v1 = a.y + b4.y;
                float v2 = a.z + b4.z, v3 = a.w + b4.w;
                v0 = v0 > 0.f ? v0 : NEG_SLOPE * v0;
                v1 = v1 > 0.f ? v1 : NEG_SLOPE * v1;
                v2 = v2 > 0.f ? v2 : NEG_SLOPE * v2;
                v3 = v3 > 0.f ? v3 : NEG_SLOPE * v3;
                float4 ex = make_float4(__expf(v0), __expf(v1), __expf(v2), __expf(v3));
                sh_exp[w][k] = ex;
                sh_src[w][k] = src;
                sum.x += ex.x; sum.y += ex.y; sum.z += ex.z; sum.w += ex.w;
            }
            // pad to even: zero-exp sentinel (contributes nothing)
            if (lane == 0 && (cnt & 1)) {
                sh_exp[w][cnt] = make_float4(0.f, 0.f, 0.f, 0.f);
                sh_src[w][cnt] = sh_src[w][0];
            }
            __syncwarp();
            int cnt2 = (cnt + 1) & ~1;
            // phase B: 2 edges per iteration, 16B gather per lane, branch-free
            #pragma unroll 4
            for (int k = 0; k < cnt2; k += 2) {
                int kk = k + e2;
                float att = ((const float*)&sh_exp[w][kk])[headq];
                int src = sh_src[w][kk];
                uint4 pk = *(const uint4*)&g_h[(size_t)src * HF + q * 8];
                float2 f0 = __half22float2(*(const __half2*)&pk.x);
                float2 f1 = __half22float2(*(const __half2*)&pk.y);
                float2 f2 = __half22float2(*(const __half2*)&pk.z);
                float2 f3 = __half22float2(*(const __half2*)&pk.w);
                acc[0] += att * f0.x; acc[1] += att * f0.y;
                acc[2] += att * f1.x; acc[3] += att * f1.y;
                acc[4] += att * f2.x; acc[5] += att * f2.y;
                acc[6] += att * f3.x; acc[7] += att * f3.y;
            }
            __syncwarp();
        }

        // combine edge-pair partials
        #pragma unroll
        for (int j = 0; j < 8; ++j)
            acc[j] += __shfl_xor_sync(0xffffffffu, acc[j], 16);

        // warp-reduce exp sums (all heads)
        #pragma unroll
        for (int off = 1; off < 32; off <<= 1) {
            sum.x += __shfl_xor_sync(0xffffffffu, sum.x, off);
            sum.y += __shfl_xor_sync(0xffffffffu, sum.y, off);
            sum.z += __shfl_xor_sync(0xffffffffu, sum.z, off);
            sum.w += __shfl_xor_sync(0xffffffffu, sum.w, off);
        }
        float sh = ((const float*)&sum)[headq];
        float inv = 1.f / (sh + EPSF);
        #pragma unroll
        for (int j = 0; j < 8; ++j) acc[j] *= inv;
    }

    if (e2 == 0) {
        float4 o0 = make_float4(acc[0], acc[1], acc[2], acc[3]);
        float4 o1 = make_float4(acc[4], acc[5], acc[6], acc[7]);
        *(float4*)&out[(size_t)n * HF + q * 8]     = o0;
        *(float4*)&out[(size_t)n * HF + q * 8 + 4] = o1;
    }
}

// ---------------- launch (fork/join two independent chains) --------------------
extern "C" void kernel_launch(void* const* d_in, const int* in_sizes, int n_in,
                              void* d_out, int out_size) {
    const float* x     = (const float*)d_in[0];
    const void*  ei    = d_in[1];
    const float* W     = (const float*)d_in[2];
    const float* a_src = (const float*)d_in[3];
    const float* a_dst = (const float*)d_in[4];
    float*       out   = (float*)d_out;

    static cudaStream_t sA = nullptr;
    static cudaEvent_t  evFork = nullptr, evJoin = nullptr;
    if (!sA) {
        cudaStreamCreateWithFlags(&sA, cudaStreamNonBlocking);
        cudaEventCreateWithFlags(&evFork, cudaEventDisableTiming);
        cudaEventCreateWithFlags(&evJoin, cudaEventDisableTiming);
    }

    // fork: branch A (CSR build) on sA, branch B (transpose+gemm) on stream 0
    cudaEventRecord(evFork, 0);
    cudaStreamWaitEvent(sA, evFork, 0);

    // branch A: CSR build
    k_zero_detect<<<(N_NODES + 255) / 256, 256, 0, sA>>>(ei);
    k_pack<<<(N_EDGES + 255) / 256, 256, 0, sA>>>(ei);
    k_scan1<<<N_SCAN_BLOCKS, SCAN_B, 0, sA>>>();
    k_scan2<<<1, 64, 0, sA>>>();
    k_scan3<<<N_SCAN_BLOCKS, SCAN_B, 0, sA>>>();
    k_scatter<<<(N_EDGES + 255) / 256, 256, 0, sA>>>();
    cudaEventRecord(evJoin, sA);

    // branch B: feature transform
    k_transpose<<<(HF * IN_F + 255) / 256, 256>>>(W);
    k_gemm<<<(N_NODES + 63) / 64, 256>>>(x, a_src, a_dst);

    // join, then aggregate
    cudaStreamWaitEvent(0, evJoin, 0);
    k_agg<<<(N_NODES + 7) / 8, 256>>>(out);
}